// round 6
// baseline (speedup 1.0000x reference)
#include <cuda_runtime.h>
#include <cuda_bf16.h>
#include <cstdint>

// ============================================================================
// HiPPO-LegT scan via chunked GEMM on mma.sync (HMMA, base sm_103).
//   c_t = A c_{t-1} + f_t B ;  out (512, 2048, 64)
// Chunk T=16:  c_{t0+j} = A^{j+1} c_in + sum_{i<=j} (A^{j-i} B) f_{t0+i}
//   => OUT[c][(j,n)] = sum_k X[c][k] * G[(j,n)][k],  K = 64 + 16 = 80
// bf16 hi/lo split, 3 MMA passes (hh, lh, hl) => rel_err ~5e-6 (validated R5).
// R6: 1 prep kernel; GEMM keeps A-frags in regs across all 16 jt, ldmatrix
// fragment loads, cp.async double-buffered G tiles.
// ============================================================================

static constexpr int TCH    = 16;
static constexpr int NCHUNK = 32;
static constexpr int NSEQ   = 2048;
static constexpr int NCOLS  = NSEQ * NCHUNK;   // 65536
static constexpr int KREAL  = 80;
static constexpr int SEQLEN = 512;
static constexpr int KPADB  = 176;             // smem row pitch bytes (88 bf16)

// ---- device scratch (static; no cudaMalloc) ----
__device__ __align__(16) float          g_Apow[17][4096];
__device__ __align__(16) float          g_Kvec[16 * 64];
__device__ __align__(16) __nv_bfloat16  g_Ghi[1024 * KREAL];
__device__ __align__(16) __nv_bfloat16  g_Glo[1024 * KREAL];
__device__ __align__(16) __nv_bfloat16  g_Xhi[(size_t)NCOLS * KREAL];
__device__ __align__(16) __nv_bfloat16  g_Xlo[(size_t)NCOLS * KREAL];

// ---- packed f32x2 helpers (phase1) ----
__device__ __forceinline__ double fma2(double a, double b, double c) {
    double d; asm("fma.rn.f32x2 %0, %1, %2, %3;" : "=d"(d) : "d"(a), "d"(b), "d"(c)); return d;
}
__device__ __forceinline__ double add2(double a, double b) {
    double d; asm("add.rn.f32x2 %0, %1, %2;" : "=d"(d) : "d"(a), "d"(b)); return d;
}
__device__ __forceinline__ double pack2(float lo, float hi) {
    double d; asm("mov.b64 %0, {%1, %2};" : "=d"(d) : "f"(lo), "f"(hi)); return d;
}
__device__ __forceinline__ void unpack2(double d, float& lo, float& hi) {
    asm("mov.b64 {%0, %1}, %2;" : "=f"(lo), "=f"(hi) : "d"(d));
}

// ---- mma / ldmatrix / cp.async ----
__device__ __forceinline__ uint32_t smem_u32(const void* p) {
    uint32_t a;
    asm("{ .reg .u64 t; cvta.to.shared.u64 t, %1; cvt.u32.u64 %0, t; }" : "=r"(a) : "l"(p));
    return a;
}
__device__ __forceinline__ void mma16816(float* d, const uint32_t* a, uint32_t b0, uint32_t b1) {
    asm volatile(
        "mma.sync.aligned.m16n8k16.row.col.f32.bf16.bf16.f32 "
        "{%0,%1,%2,%3}, {%4,%5,%6,%7}, {%8,%9}, {%0,%1,%2,%3};\n"
        : "+f"(d[0]), "+f"(d[1]), "+f"(d[2]), "+f"(d[3])
        : "r"(a[0]), "r"(a[1]), "r"(a[2]), "r"(a[3]), "r"(b0), "r"(b1));
}
__device__ __forceinline__ void ldsm_x4(uint32_t* r, uint32_t addr) {
    asm volatile("ldmatrix.sync.aligned.m8n8.x4.shared.b16 {%0,%1,%2,%3}, [%4];"
                 : "=r"(r[0]), "=r"(r[1]), "=r"(r[2]), "=r"(r[3]) : "r"(addr));
}
__device__ __forceinline__ void cp_async16(uint32_t smem, const void* g) {
    asm volatile("cp.async.cg.shared.global [%0], [%1], 16;" :: "r"(smem), "l"(g));
}
__device__ __forceinline__ void cp_commit() { asm volatile("cp.async.commit_group;" ::: "memory"); }
__device__ __forceinline__ void cp_wait0()  { asm volatile("cp.async.wait_group 0;"  ::: "memory"); }

__device__ __forceinline__ void bf16split(float x, __nv_bfloat16& h, __nv_bfloat16& l) {
    h = __float2bfloat16(x);
    l = __float2bfloat16(x - __bfloat162float(h));
}

// ============================================================================
// Prep: A powers 1..16, Kvec, G matrix.  ONE CTA, 1024 threads.
// ============================================================================
__global__ __launch_bounds__(1024) void prep_kernel(const float* __restrict__ A,
                                                    const float* __restrict__ Bvec) {
    __shared__ __align__(16) float sA[4096];
    __shared__ __align__(16) float sP[4096];
    __shared__ __align__(16) float sK[16 * 64];
    const int t = threadIdx.x;

    for (int i = t; i < 4096; i += 1024) {
        const float v = A[i];
        sA[i] = v; sP[i] = v; g_Apow[1][i] = v;
    }
    if (t < 64) sK[t] = Bvec[t];
    __syncthreads();

    // A^p = A^(p-1) @ A, p = 2..16 (each thread: 4 output elements)
    for (int p = 2; p <= 16; p++) {
        float acc[4];
        #pragma unroll
        for (int i = 0; i < 4; i++) {
            const int e = t + 1024 * i, row = e >> 6, col = e & 63;
            float s0 = 0.f, s1 = 0.f;
            #pragma unroll
            for (int m = 0; m < 64; m += 2) {
                s0 = fmaf(sP[row * 64 + m],     sA[m * 64 + col],       s0);
                s1 = fmaf(sP[row * 64 + m + 1], sA[(m + 1) * 64 + col], s1);
            }
            acc[i] = s0 + s1;
        }
        __syncthreads();
        #pragma unroll
        for (int i = 0; i < 4; i++) {
            const int e = t + 1024 * i;
            sP[e] = acc[i];
            g_Apow[p][e] = acc[i];
        }
        __syncthreads();
    }

    // Kvec[d] = A @ Kvec[d-1], d = 1..15
    for (int d = 1; d < 16; d++) {
        float acc = 0.f;
        if (t < 64) {
            #pragma unroll
            for (int m = 0; m < 64; m++) acc = fmaf(sA[t * 64 + m], sK[(d - 1) * 64 + m], acc);
        }
        __syncthreads();
        if (t < 64) sK[d * 64 + t] = acc;
        __syncthreads();
    }
    g_Kvec[t] = sK[t];           // 1024 entries, 1 per thread

    // G build: thread t -> row r = j*64 + n
    {
        const int r = t, j = r >> 6, n = r & 63;
        __nv_bfloat16 h, l;
        const float4* ap = reinterpret_cast<const float4*>(&g_Apow[j + 1][n * 64]);
        #pragma unroll
        for (int v = 0; v < 16; v++) {
            const float4 a = ap[v];
            bf16split(a.x, h, l); g_Ghi[r * KREAL + 4 * v + 0] = h; g_Glo[r * KREAL + 4 * v + 0] = l;
            bf16split(a.y, h, l); g_Ghi[r * KREAL + 4 * v + 1] = h; g_Glo[r * KREAL + 4 * v + 1] = l;
            bf16split(a.z, h, l); g_Ghi[r * KREAL + 4 * v + 2] = h; g_Glo[r * KREAL + 4 * v + 2] = l;
            bf16split(a.w, h, l); g_Ghi[r * KREAL + 4 * v + 3] = h; g_Glo[r * KREAL + 4 * v + 3] = l;
        }
        #pragma unroll
        for (int i = 0; i < 16; i++) {
            const int d = j - i;
            const float v = (d < 0) ? 0.0f : sK[d * 64 + n];
            bf16split(v, h, l);
            g_Ghi[r * KREAL + 64 + i] = h;
            g_Glo[r * KREAL + 64 + i] = l;
        }
    }
}

// ============================================================================
// Phase 1: boundary scan (fp32, f32x2) + X build (bf16 hi/lo). 2048 x 64.
// ============================================================================
__global__ __launch_bounds__(64) void phase1_kernel(const float* __restrict__ xin) {
    const int seq = blockIdx.x, n = threadIdx.x;
    __shared__ __align__(16) float c_sm[2][64];
    __shared__ __align__(16) float f_sm[2][16];

    double a16[32];
    {
        const double* r = reinterpret_cast<const double*>(&g_Apow[16][n * 64]);
        #pragma unroll
        for (int i = 0; i < 32; i++) a16[i] = r[i];
    }
    double wp[8];
    #pragma unroll
    for (int i = 0; i < 8; i++)
        wp[i] = pack2(g_Kvec[(15 - 2 * i) * 64 + n], g_Kvec[(14 - 2 * i) * 64 + n]);

    float cmy = 0.0f;
    c_sm[0][n] = 0.0f;

    for (int k = 0; k < NCHUNK; k++) {
        const int buf = k & 1;
        const size_t col = (size_t)k * NSEQ + seq;
        {
            __nv_bfloat16 h = __float2bfloat16(cmy);
            g_Xhi[col * KREAL + n] = h;
            g_Xlo[col * KREAL + n] = __float2bfloat16(cmy - __bfloat162float(h));
        }
        if (n < 16) {
            const float f = xin[(size_t)seq * SEQLEN + k * TCH + n];
            f_sm[buf][n] = f;
            __nv_bfloat16 h = __float2bfloat16(f);
            g_Xhi[col * KREAL + 64 + n] = h;
            g_Xlo[col * KREAL + 64 + n] = __float2bfloat16(f - __bfloat162float(h));
        }
        __syncthreads();

        const double2* cp = reinterpret_cast<const double2*>(c_sm[buf]);
        double acc0 = 0.0, acc1 = 0.0, acc2 = 0.0, acc3 = 0.0;
        #pragma unroll
        for (int i = 0; i < 8; i++) {
            const double2 ca = cp[2 * i], cb = cp[2 * i + 1];
            acc0 = fma2(a16[4 * i],     ca.x, acc0);
            acc1 = fma2(a16[4 * i + 1], ca.y, acc1);
            acc2 = fma2(a16[4 * i + 2], cb.x, acc2);
            acc3 = fma2(a16[4 * i + 3], cb.y, acc3);
        }
        const double* fp = reinterpret_cast<const double*>(f_sm[buf]);
        acc0 = fma2(wp[0], fp[0], acc0); acc1 = fma2(wp[1], fp[1], acc1);
        acc2 = fma2(wp[2], fp[2], acc2); acc3 = fma2(wp[3], fp[3], acc3);
        acc0 = fma2(wp[4], fp[4], acc0); acc1 = fma2(wp[5], fp[5], acc1);
        acc2 = fma2(wp[6], fp[6], acc2); acc3 = fma2(wp[7], fp[7], acc3);

        const double s = add2(add2(acc0, acc1), add2(acc2, acc3));
        float x, y;
        unpack2(s, x, y);
        cmy = x + y;
        c_sm[buf ^ 1][n] = cmy;
    }
}

// ============================================================================
// GEMM: 1024 CTAs x 128 thr.  CTA: 64 X-cols, loops all 16 jt (64 G rows each).
// A-fragments (X) in registers across jt loop; G double-buffered via cp.async.
// Smem arena 45056 B: prologue [Xhi 11264 | Xlo 11264 | buf1 22528],
// steady state [buf0 22528 | buf1 22528] (X region reused after A-frag load).
// ============================================================================
__global__ __launch_bounds__(128) void gemm_kernel(float* __restrict__ out) {
    __shared__ __align__(16) char arena[45056];

    const int tid = threadIdx.x;
    const int w = tid >> 5, l = tid & 31;
    const int mbase = blockIdx.x * 64;
    const uint32_t base = smem_u32(arena);

    const int half = tid >> 6;            // 0 = hi, 1 = lo
    const int row  = tid & 63;

    // ---- prologue: cp.async X tile -> [0,22528), G(0) tile -> buf1 ----
    {
        const __nv_bfloat16* xs = (half ? g_Xlo : g_Xhi) + (size_t)(mbase + row) * KREAL;
        const uint32_t xd = base + half * 11264 + row * KPADB;
        #pragma unroll
        for (int v = 0; v < 10; v++) cp_async16(xd + v * 16, (const char*)xs + v * 16);
        const __nv_bfloat16* gs = (half ? g_Glo : g_Ghi) + (size_t)row * KREAL;
        const uint32_t gd = base + 22528 + half * 11264 + row * KPADB;
        #pragma unroll
        for (int v = 0; v < 10; v++) cp_async16(gd + v * 16, (const char*)gs + v * 16);
        cp_commit(); cp_wait0();
    }
    __syncthreads();

    // ---- A fragments from X (held across all jt) ----
    const int m0w = (w & 1) * 32;
    const int n0w = (w >> 1) * 32;
    uint32_t ah[2][5][4], al[2][5][4];
    {
        const uint32_t aoff = base + (uint32_t)(m0w + (l & 15)) * KPADB + ((l >> 4) * 16);
        #pragma unroll
        for (int mt = 0; mt < 2; mt++)
            #pragma unroll
            for (int ks = 0; ks < 5; ks++) {
                const uint32_t ad = aoff + mt * (16 * KPADB) + ks * 32;
                ldsm_x4(ah[mt][ks], ad);
                ldsm_x4(al[mt][ks], ad + 11264);
            }
    }
    __syncthreads();   // X region free -> becomes buf0

    // B lane address base (within a buffer)
    const uint32_t boff = (uint32_t)(n0w + (l & 7) + ((l & 16) >> 1)) * KPADB + ((l & 8) << 1);

    const int chunk = mbase >> 11;
    const int seqb  = mbase & 2047;

    for (int i = 0; i < 16; i++) {
        const int cur = (i + 1) & 1;       // i=0 -> buf1

        if (i < 15) {                       // prefetch G(i+1) -> other buffer
            const __nv_bfloat16* gs = (half ? g_Glo : g_Ghi) + (size_t)((i + 1) * 64 + row) * KREAL;
            const uint32_t gd = base + (cur ^ 1) * 22528 + half * 11264 + row * KPADB;
            #pragma unroll
            for (int v = 0; v < 10; v++) cp_async16(gd + v * 16, (const char*)gs + v * 16);
            cp_commit();
        }

        // ---- compute jt = i from buffer `cur` ----
        float acc[2][4][4];
        #pragma unroll
        for (int mt = 0; mt < 2; mt++)
            #pragma unroll
            for (int nt = 0; nt < 4; nt++)
                #pragma unroll
                for (int q = 0; q < 4; q++) acc[mt][nt][q] = 0.0f;

        const uint32_t gb = base + cur * 22528 + boff;
        #pragma unroll
        for (int ks = 0; ks < 5; ks++) {
            uint32_t bh[2][4], bl[2][4];
            #pragma unroll
            for (int p = 0; p < 2; p++) {
                const uint32_t bd = gb + p * (16 * KPADB) + ks * 32;
                ldsm_x4(bh[p], bd);
                ldsm_x4(bl[p], bd + 11264);
            }
            #pragma unroll
            for (int mt = 0; mt < 2; mt++)
                #pragma unroll
                for (int p = 0; p < 2; p++)
                    #pragma unroll
                    for (int hh = 0; hh < 2; hh++) {
                        const int nt = p * 2 + hh;
                        mma16816(acc[mt][nt], ah[mt][ks], bh[p][2 * hh], bh[p][2 * hh + 1]);
                        mma16816(acc[mt][nt], al[mt][ks], bh[p][2 * hh], bh[p][2 * hh + 1]);
                        mma16816(acc[mt][nt], ah[mt][ks], bl[p][2 * hh], bl[p][2 * hh + 1]);
                    }
        }

        // ---- epilogue for jt = i ----
        {
            float* obase = out + (size_t)(chunk * TCH + i) * NSEQ * 64 + n0w + (l & 3) * 2;
            #pragma unroll
            for (int mt = 0; mt < 2; mt++)
                #pragma unroll
                for (int s = 0; s < 2; s++) {
                    const int m = m0w + mt * 16 + (l >> 2) + s * 8;
                    float* ob = obase + (size_t)(seqb + m) * 64;
                    #pragma unroll
                    for (int nt = 0; nt < 4; nt++) {
                        float2 v = make_float2(acc[mt][nt][2 * s], acc[mt][nt][2 * s + 1]);
                        *reinterpret_cast<float2*>(ob + nt * 8) = v;
                    }
                }
        }

        if (i < 15) cp_wait0();
        __syncthreads();
    }
}

// ============================================================================
extern "C" void kernel_launch(void* const* d_in, const int* in_sizes, int n_in,
                              void* d_out, int out_size) {
    const float* xin  = (const float*)d_in[0];  // (16,128,512)
    const float* Amat = (const float*)d_in[1];  // (64,64)
    const float* Bvec = (const float*)d_in[2];  // (64,)
    float* out = (float*)d_out;                 // (512,16,128,64)

    prep_kernel<<<1, 1024>>>(Amat, Bvec);
    phase1_kernel<<<NSEQ, 64>>>(xin);
    gemm_kernel<<<NCOLS / 64, 128>>>(out);
}

// round 7
// speedup vs baseline: 1.8031x; 1.8031x over previous
#include <cuda_runtime.h>
#include <cuda_fp16.h>
#include <cstdint>

// ============================================================================
// HiPPO-LegT scan via chunked GEMM on mma.sync (HMMA fp16, base sm_103).
//   c_t = A c_{t-1} + f_t B ;  out (512, 2048, 64)
// Chunk T=16:  OUT[c][(j,n)] = sum_k X[c][k] * G[(j,n)][k],  K = 80.
// fp16 2-pass: X = Xhi + Xlo (two-term fp16 split, near-exact), G = fp16.
//   out = Xhi.Gh + Xlo.Gh   (error ~2^-12 from G rounding -> rel_err ~1e-4)
// Prep: multi-CTA log-doubling A-powers (R5-validated), G build, boundary
// scan, then register-A-resident GEMM with cp.async double-buffered G.
// ============================================================================

static constexpr int TCH    = 16;
static constexpr int NCHUNK = 32;
static constexpr int NSEQ   = 2048;
static constexpr int NCOLS  = NSEQ * NCHUNK;   // 65536
static constexpr int KREAL  = 80;
static constexpr int SEQLEN = 512;
static constexpr int KPADB  = 176;             // smem row pitch bytes (88 halves)

// ---- device scratch (static; no cudaMalloc) ----
__device__ __align__(16) float   g_Apow[17][4096];
__device__ __align__(16) float   g_Kvec[16 * 64];
__device__ __align__(16) __half  g_Gh [1024 * KREAL];
__device__ __align__(16) __half  g_Xhi[(size_t)NCOLS * KREAL];
__device__ __align__(16) __half  g_Xlo[(size_t)NCOLS * KREAL];

// ---- packed f32x2 helpers (phase1) ----
__device__ __forceinline__ double fma2(double a, double b, double c) {
    double d; asm("fma.rn.f32x2 %0, %1, %2, %3;" : "=d"(d) : "d"(a), "d"(b), "d"(c)); return d;
}
__device__ __forceinline__ double add2(double a, double b) {
    double d; asm("add.rn.f32x2 %0, %1, %2;" : "=d"(d) : "d"(a), "d"(b)); return d;
}
__device__ __forceinline__ double pack2(float lo, float hi) {
    double d; asm("mov.b64 %0, {%1, %2};" : "=d"(d) : "f"(lo), "f"(hi)); return d;
}
__device__ __forceinline__ void unpack2(double d, float& lo, float& hi) {
    asm("mov.b64 {%0, %1}, %2;" : "=f"(lo), "=f"(hi) : "d"(d));
}

// ---- mma / ldmatrix / cp.async ----
__device__ __forceinline__ uint32_t smem_u32(const void* p) {
    uint32_t a;
    asm("{ .reg .u64 t; cvta.to.shared.u64 t, %1; cvt.u32.u64 %0, t; }" : "=r"(a) : "l"(p));
    return a;
}
__device__ __forceinline__ void mma16816(float* d, const uint32_t* a, uint32_t b0, uint32_t b1) {
    asm volatile(
        "mma.sync.aligned.m16n8k16.row.col.f32.f16.f16.f32 "
        "{%0,%1,%2,%3}, {%4,%5,%6,%7}, {%8,%9}, {%0,%1,%2,%3};\n"
        : "+f"(d[0]), "+f"(d[1]), "+f"(d[2]), "+f"(d[3])
        : "r"(a[0]), "r"(a[1]), "r"(a[2]), "r"(a[3]), "r"(b0), "r"(b1));
}
__device__ __forceinline__ void ldsm_x4(uint32_t* r, uint32_t addr) {
    asm volatile("ldmatrix.sync.aligned.m8n8.x4.shared.b16 {%0,%1,%2,%3}, [%4];"
                 : "=r"(r[0]), "=r"(r[1]), "=r"(r[2]), "=r"(r[3]) : "r"(addr));
}
__device__ __forceinline__ void cp_async16(uint32_t smem, const void* g) {
    asm volatile("cp.async.cg.shared.global [%0], [%1], 16;" :: "r"(smem), "l"(g));
}
__device__ __forceinline__ void cp_commit() { asm volatile("cp.async.commit_group;" ::: "memory"); }
__device__ __forceinline__ void cp_wait0()  { asm volatile("cp.async.wait_group 0;"  ::: "memory"); }

// ============================================================================
// A-power doubling level:  A^(Bv+q) = A^Bv * A^q  for q = 1..Bv.
// grid = Bv*16 CTAs, 256 threads; each CTA computes 256 output elements.
// (R5-validated.)
// ============================================================================
__global__ __launch_bounds__(256) void pow_level_kernel(const float* __restrict__ A, int Bv) {
    __shared__ __align__(16) float sL[4096];
    __shared__ __align__(16) float sR[4096];
    const int q   = (blockIdx.x >> 4) + 1;
    const int dst = Bv + q;
    const float* Lp = (Bv == 1) ? A : g_Apow[Bv];
    const float* Rp = (q  == 1) ? A : g_Apow[q];
    const int tid = threadIdx.x;
    for (int i = tid; i < 4096; i += 256) { sL[i] = Lp[i]; sR[i] = Rp[i]; }
    __syncthreads();

    const int e   = (blockIdx.x & 15) * 256 + tid;
    const int row = e >> 6, col = e & 63;
    float a0 = 0.f, a1 = 0.f, a2 = 0.f, a3 = 0.f;
    #pragma unroll
    for (int m = 0; m < 64; m += 4) {
        a0 = fmaf(sL[row * 64 + m],     sR[(m)     * 64 + col], a0);
        a1 = fmaf(sL[row * 64 + m + 1], sR[(m + 1) * 64 + col], a1);
        a2 = fmaf(sL[row * 64 + m + 2], sR[(m + 2) * 64 + col], a2);
        a3 = fmaf(sL[row * 64 + m + 3], sR[(m + 3) * 64 + col], a3);
    }
    g_Apow[dst][e] = (a0 + a1) + (a2 + a3);
    if (Bv == 1) g_Apow[1][e] = A[e];
}

// ============================================================================
// G build (+ Kvec).  17 CTAs x 64 threads.  G stored as single fp16 (hi).
// ============================================================================
__global__ __launch_bounds__(64) void gbuild_kernel(const float* __restrict__ Bvec) {
    __shared__ __align__(16) float sB[64];
    const int j = blockIdx.x, n = threadIdx.x;
    sB[n] = Bvec[n];
    __syncthreads();

    auto dotAB = [&](int d) -> float {
        const float4* ap = reinterpret_cast<const float4*>(&g_Apow[d][n * 64]);
        const float4* bp = reinterpret_cast<const float4*>(sB);
        float s0 = 0.f, s1 = 0.f, s2 = 0.f, s3 = 0.f;
        #pragma unroll
        for (int v = 0; v < 16; v++) {
            float4 a = ap[v], b = bp[v];
            s0 = fmaf(a.x, b.x, s0); s1 = fmaf(a.y, b.y, s1);
            s2 = fmaf(a.z, b.z, s2); s3 = fmaf(a.w, b.w, s3);
        }
        return (s0 + s1) + (s2 + s3);
    };

    if (j < 16) {
        const int r = j * 64 + n;
        for (int k = 0; k < 64; k++)
            g_Gh[r * KREAL + k] = __float2half(g_Apow[j + 1][n * 64 + k]);
        for (int i = 0; i < 16; i++) {
            const int d = j - i;
            const float v = (d < 0) ? 0.0f : ((d == 0) ? sB[n] : dotAB(d));
            g_Gh[r * KREAL + 64 + i] = __float2half(v);
        }
    } else {
        for (int d = 0; d < 16; d++)
            g_Kvec[d * 64 + n] = (d == 0) ? sB[n] : dotAB(d);
    }
}

// ============================================================================
// Phase 1: boundary scan (fp32, f32x2) + X build (fp16 hi/lo). 2048 x 64.
// ============================================================================
__global__ __launch_bounds__(64) void phase1_kernel(const float* __restrict__ xin) {
    const int seq = blockIdx.x, n = threadIdx.x;
    __shared__ __align__(16) float c_sm[2][64];
    __shared__ __align__(16) float f_sm[2][16];

    double a16[32];
    {
        const double* r = reinterpret_cast<const double*>(&g_Apow[16][n * 64]);
        #pragma unroll
        for (int i = 0; i < 32; i++) a16[i] = r[i];
    }
    double wp[8];
    #pragma unroll
    for (int i = 0; i < 8; i++)
        wp[i] = pack2(g_Kvec[(15 - 2 * i) * 64 + n], g_Kvec[(14 - 2 * i) * 64 + n]);

    float cmy = 0.0f;
    c_sm[0][n] = 0.0f;

    for (int k = 0; k < NCHUNK; k++) {
        const int buf = k & 1;
        const size_t col = (size_t)k * NSEQ + seq;
        {
            const __half h = __float2half(cmy);
            g_Xhi[col * KREAL + n] = h;
            g_Xlo[col * KREAL + n] = __float2half(cmy - __half2float(h));
        }
        if (n < 16) {
            const float f = xin[(size_t)seq * SEQLEN + k * TCH + n];
            f_sm[buf][n] = f;
            const __half h = __float2half(f);
            g_Xhi[col * KREAL + 64 + n] = h;
            g_Xlo[col * KREAL + 64 + n] = __float2half(f - __half2float(h));
        }
        __syncthreads();

        const double2* cp = reinterpret_cast<const double2*>(c_sm[buf]);
        double acc0 = 0.0, acc1 = 0.0, acc2 = 0.0, acc3 = 0.0;
        #pragma unroll
        for (int i = 0; i < 8; i++) {
            const double2 ca = cp[2 * i], cb = cp[2 * i + 1];
            acc0 = fma2(a16[4 * i],     ca.x, acc0);
            acc1 = fma2(a16[4 * i + 1], ca.y, acc1);
            acc2 = fma2(a16[4 * i + 2], cb.x, acc2);
            acc3 = fma2(a16[4 * i + 3], cb.y, acc3);
        }
        const double* fp = reinterpret_cast<const double*>(f_sm[buf]);
        acc0 = fma2(wp[0], fp[0], acc0); acc1 = fma2(wp[1], fp[1], acc1);
        acc2 = fma2(wp[2], fp[2], acc2); acc3 = fma2(wp[3], fp[3], acc3);
        acc0 = fma2(wp[4], fp[4], acc0); acc1 = fma2(wp[5], fp[5], acc1);
        acc2 = fma2(wp[6], fp[6], acc2); acc3 = fma2(wp[7], fp[7], acc3);

        const double s = add2(add2(acc0, acc1), add2(acc2, acc3));
        float x, y;
        unpack2(s, x, y);
        cmy = x + y;
        c_sm[buf ^ 1][n] = cmy;
    }
}

// ============================================================================
// GEMM: 1024 CTAs x 128 thr.  CTA: 64 X-cols, loops all 16 jt.
// Arena: [Xhi 11264 | Xlo 11264 | Gbuf0 11264 | Gbuf1 11264] = 45056 B.
// 2 fp16 passes (Xhi.Gh + Xlo.Gh): 16 MMA per (jt, ks).
// ============================================================================
__global__ __launch_bounds__(128) void gemm_kernel(float* __restrict__ out) {
    __shared__ __align__(16) char arena[45056];

    const int tid = threadIdx.x;
    const int w = tid >> 5, l = tid & 31;
    const int mbase = blockIdx.x * 64;
    const uint32_t base = smem_u32(arena);

    const int hf  = tid >> 6;             // 0 / 1
    const int row = tid & 63;

    // ---- prologue: X (hi+lo) and G(0) -> buf0 ----
    {
        const __half* xs = (hf ? g_Xlo : g_Xhi) + (size_t)(mbase + row) * KREAL;
        const uint32_t xd = base + hf * 11264 + row * KPADB;
        #pragma unroll
        for (int v = 0; v < 10; v++) cp_async16(xd + v * 16, (const char*)xs + v * 16);

        const __half* gs = g_Gh + (size_t)row * KREAL;
        const uint32_t gd = base + 22528 + row * KPADB;
        #pragma unroll
        for (int v = 0; v < 5; v++) {
            const int vv = hf * 5 + v;
            cp_async16(gd + vv * 16, (const char*)gs + vv * 16);
        }
        cp_commit(); cp_wait0();
    }
    __syncthreads();

    // ---- A fragments (X hi+lo) held across all jt ----
    const int m0w = (w & 1) * 32;
    const int n0w = (w >> 1) * 32;
    uint32_t ah[2][5][4], al[2][5][4];
    {
        const uint32_t aoff = base + (uint32_t)(m0w + (l & 15)) * KPADB + ((l >> 4) * 16);
        #pragma unroll
        for (int mt = 0; mt < 2; mt++)
            #pragma unroll
            for (int ks = 0; ks < 5; ks++) {
                const uint32_t ad = aoff + mt * (16 * KPADB) + ks * 32;
                ldsm_x4(ah[mt][ks], ad);
                ldsm_x4(al[mt][ks], ad + 11264);
            }
    }

    const uint32_t boff = (uint32_t)(n0w + (l & 7) + ((l & 16) >> 1)) * KPADB + ((l & 8) << 1);
    const int chunk = mbase >> 11;
    const int seqb  = mbase & 2047;

    for (int i = 0; i < 16; i++) {
        const int cur = i & 1;

        if (i < 15) {   // prefetch G(i+1) into the other buffer
            const __half* gs = g_Gh + (size_t)((i + 1) * 64 + row) * KREAL;
            const uint32_t gd = base + 22528 + (cur ^ 1) * 11264 + row * KPADB;
            #pragma unroll
            for (int v = 0; v < 5; v++) {
                const int vv = hf * 5 + v;
                cp_async16(gd + vv * 16, (const char*)gs + vv * 16);
            }
            cp_commit();
        }

        float acc[2][4][4];
        #pragma unroll
        for (int mt = 0; mt < 2; mt++)
            #pragma unroll
            for (int nt = 0; nt < 4; nt++)
                #pragma unroll
                for (int q = 0; q < 4; q++) acc[mt][nt][q] = 0.0f;

        const uint32_t gb = base + 22528 + cur * 11264 + boff;
        #pragma unroll
        for (int ks = 0; ks < 5; ks++) {
            uint32_t bh[2][4];
            #pragma unroll
            for (int p = 0; p < 2; p++)
                ldsm_x4(bh[p], gb + p * (16 * KPADB) + ks * 32);
            #pragma unroll
            for (int mt = 0; mt < 2; mt++)
                #pragma unroll
                for (int p = 0; p < 2; p++)
                    #pragma unroll
                    for (int hh = 0; hh < 2; hh++) {
                        const int nt = p * 2 + hh;
                        mma16816(acc[mt][nt], ah[mt][ks], bh[p][2 * hh], bh[p][2 * hh + 1]);
                        mma16816(acc[mt][nt], al[mt][ks], bh[p][2 * hh], bh[p][2 * hh + 1]);
                    }
        }

        // ---- epilogue for jt = i ----
        {
            float* obase = out + (size_t)(chunk * TCH + i) * NSEQ * 64 + n0w + (l & 3) * 2;
            #pragma unroll
            for (int mt = 0; mt < 2; mt++)
                #pragma unroll
                for (int s = 0; s < 2; s++) {
                    const int m = m0w + mt * 16 + (l >> 2) + s * 8;
                    float* ob = obase + (size_t)(seqb + m) * 64;
                    #pragma unroll
                    for (int nt = 0; nt < 4; nt++) {
                        float2 v = make_float2(acc[mt][nt][2 * s], acc[mt][nt][2 * s + 1]);
                        *reinterpret_cast<float2*>(ob + nt * 8) = v;
                    }
                }
        }

        if (i < 15) cp_wait0();
        __syncthreads();
    }
}

// ============================================================================
extern "C" void kernel_launch(void* const* d_in, const int* in_sizes, int n_in,
                              void* d_out, int out_size) {
    const float* xin  = (const float*)d_in[0];  // (16,128,512)
    const float* Amat = (const float*)d_in[1];  // (64,64)
    const float* Bvec = (const float*)d_in[2];  // (64,)
    float* out = (float*)d_out;                 // (512,16,128,64)

    pow_level_kernel<<<16,  256>>>(Amat, 1);   // A^2 (+ A^1)
    pow_level_kernel<<<32,  256>>>(Amat, 2);   // A^3..A^4
    pow_level_kernel<<<64,  256>>>(Amat, 4);   // A^5..A^8
    pow_level_kernel<<<128, 256>>>(Amat, 8);   // A^9..A^16
    gbuild_kernel<<<17, 64>>>(Bvec);
    phase1_kernel<<<NSEQ, 64>>>(xin);
    gemm_kernel<<<NCOLS / 64, 128>>>(out);
}